// round 15
// baseline (speedup 1.0000x reference)
#include <cuda_runtime.h>
#include <cuda_bf16.h>
#include <math.h>
#include <stdint.h>

#define BB   8192
#define MM   10
#define NNB  9
#define FIN  128
#define DXX  128
#define KK   64
#define LL   32
#define NALL 100000
#define GN   192
#define KCAT 1344     // feat 576 | str 576 | root 128 | rad 18 + pad 46

// ------------------- device scratch -------------------
__device__ float g_tnxT[FIN*LL];
__device__ float g_tnsT[NNB*LL];
__device__ float g_biasv[GN];
__device__ float g_cSg[64];
__device__ float g_cCb[64];
__device__ float g_Hraw[(size_t)BB*MM*GN];
__device__ __align__(16) __nv_bfloat16 g_BtileH[2*GN*136];

__device__ __align__(16) __nv_bfloat16 g_AbH[(size_t)BB*KCAT];
__device__ __align__(16) __nv_bfloat16 g_AbL[(size_t)BB*KCAT];
__device__ __align__(16) __nv_bfloat16 g_PbH[KK*KCAT];
__device__ __align__(16) __nv_bfloat16 g_PbL[KK*KCAT];

__device__ float g_hproto_sq[KK];
__device__ float g_hp[KK*32];
__device__ float g_hrootsq[BB];
__device__ float g_hb[BB*32];
__device__ float g_alpha[BB];
__device__ float g_T1feat[BB];
__device__ float g_T1str[BB];
__device__ float g_Srad[BB];

// ------------------- helpers -------------------
__device__ __forceinline__ void sort9(float* v){
  for (int a=1;a<NNB;a++){
    float x=v[a]; int c=a-1;
    while (c>=0 && v[c]>x){ v[c+1]=v[c]; c--; }
    v[c+1]=x;
  }
}
__device__ __forceinline__ void argsort9(const float* v, int* ord){
  for (int a=0;a<NNB;a++) ord[a]=a;
  for (int a=1;a<NNB;a++){
    int o=ord[a]; float x=v[o]; int c=a-1;
    while (c>=0 && v[ord[c]]>x){ ord[c+1]=ord[c]; c--; }
    ord[c+1]=o;
  }
}
__device__ __forceinline__ float wredsum(float v){
  #pragma unroll
  for (int o=16;o;o>>=1) v += __shfl_xor_sync(0xffffffffu, v, o);
  return v;
}
__device__ __forceinline__ void ln_rows(float (*sH)[FIN], int nrows,
                                        const float* g, const float* b, int t){
  int w = t>>5, lane = t&31;
  for (int r=w; r<nrows; r+=4){
    float s=0.f;
    for (int j=lane;j<FIN;j+=32) s += sH[r][j];
    s = wredsum(s);
    float mu = s*(1.f/FIN);
    float s2=0.f;
    for (int j=lane;j<FIN;j+=32){ float d=sH[r][j]-mu; s2 += d*d; }
    s2 = wredsum(s2);
    float rstd = rsqrtf(s2*(1.f/FIN)+1e-5f);
    for (int j=lane;j<FIN;j+=32) sH[r][j] = (sH[r][j]-mu)*rstd*g[j] + b[j];
  }
}
__device__ __forceinline__ uint32_t smem_u32(const void* p){
  uint32_t a;
  asm("{ .reg .u64 t; cvta.to.shared.u64 t, %1; cvt.u32.u64 %0, t; }" : "=r"(a) : "l"(p));
  return a;
}
__device__ __forceinline__ void st_hl(__nv_bfloat16* H, __nv_bfloat16* L, size_t i, float v){
  __nv_bfloat16 h = __float2bfloat16(v);
  H[i]=h; L[i]=__float2bfloat16(v - __bfloat162float(h));
}
// ---- sm_80-compatible tensor core ops ----
__device__ __forceinline__ void ldsm_x4(uint32_t* r, uint32_t addr){
  asm volatile("ldmatrix.sync.aligned.m8n8.x4.shared.b16 {%0,%1,%2,%3}, [%4];"
    : "=r"(r[0]),"=r"(r[1]),"=r"(r[2]),"=r"(r[3]) : "r"(addr));
}
__device__ __forceinline__ void ldsm_x2(uint32_t* r, uint32_t addr){
  asm volatile("ldmatrix.sync.aligned.m8n8.x2.shared.b16 {%0,%1}, [%2];"
    : "=r"(r[0]),"=r"(r[1]) : "r"(addr));
}
__device__ __forceinline__ void mma16816(float* c, const uint32_t* a, const uint32_t* b){
  asm volatile(
    "mma.sync.aligned.m16n8k16.row.col.f32.bf16.bf16.f32 "
    "{%0,%1,%2,%3}, {%4,%5,%6,%7}, {%8,%9}, {%0,%1,%2,%3};"
    : "+f"(c[0]),"+f"(c[1]),"+f"(c[2]),"+f"(c[3])
    : "r"(a[0]),"r"(a[1]),"r"(a[2]),"r"(a[3]), "r"(b[0]),"r"(b[1]));
}

// ------------------- kernel 0: prep -------------------
__global__ void k_prep(const float* Wlin, const float* blin,
                       const float* lng, const float* lnb,
                       const float* an_w1, const float* theta_x, const float* theta_s){
  int bid = blockIdx.x, t = threadIdx.x;
  if (bid < 32){
    __shared__ float sInv[32];
    int wq = t>>5, lq = t&31;
    for (int row=wq; row<32; row+=8){
      float s=0.f;
      for (int j=lq;j<FIN;j+=32){ float v=theta_x[row*FIN+j]; s+=v*v; }
      s = wredsum(s);
      if (lq==0) sInv[row] = 1.0f/sqrtf(s);
    }
    __syncthreads();
    int out = bid*256 + t;
    int i = out >> 6, c = out & 63;
    float acc = 0.f;
    if (c < 32){
      for (int d=0; d<FIN; d++)
        acc += Wlin[i*DXX + d] * (lng[d]*theta_x[c*FIN + d]);
      acc *= sInv[c];
    } else {
      for (int d=0; d<FIN; d++)
        acc += Wlin[i*DXX + d] * (lng[d]*an_w1[d*32 + (c-32)]);
    }
    __nv_bfloat16 hb = __float2bfloat16(acc);
    __nv_bfloat16 lb = __float2bfloat16(acc - __bfloat162float(hb));
    int n = 128 + c;
    g_BtileH[(0*GN + n)*136 + i] = hb;
    g_BtileH[(1*GN + n)*136 + i] = lb;
  } else if (bid < 40){
    int base = (bid-32)*2048;
    for (int it=0; it<8; it++){
      int u = base + t + it*256;
      float v = Wlin[u];
      int k = u >> 7, n = u & 127;
      __nv_bfloat16 hb = __float2bfloat16(v);
      __nv_bfloat16 lb = __float2bfloat16(v - __bfloat162float(hb));
      g_BtileH[(0*GN + n)*136 + k] = hb;
      g_BtileH[(1*GN + n)*136 + k] = lb;
    }
  } else if (bid == 40){
    if (t < 128) g_biasv[t] = blin[t];
    float inv = 1.f;
    if (t < 32){
      float s=0.f;
      for (int d=0; d<FIN; d++){ float v=theta_x[t*FIN+d]; s+=v*v; }
      inv = 1.0f/sqrtf(s);
    }
    if (t < 64){
      float bs=0.f, sg=0.f, cb=0.f;
      for (int d=0; d<FIN; d++){
        float th = (t<32) ? theta_x[t*FIN+d]*inv : an_w1[d*32 + (t-32)];
        float v = lng[d]*th;
        bs += blin[d]*v;
        sg += v;
        cb += lnb[d]*th;
      }
      g_biasv[128+t]=bs; g_cSg[t]=sg; g_cCb[t]=cb;
    }
  } else {
    int w=t>>5, lane=t&31;
    for (int row=w; row<LL; row+=8){
      float s=0.f;
      for (int j=lane;j<FIN;j+=32){ float v=theta_x[row*FIN+j]; s+=v*v; }
      s = wredsum(s);
      float inv = 1.0f/sqrtf(s);
      for (int j=lane;j<FIN;j+=32) g_tnxT[j*LL+row] = theta_x[row*FIN+j]*inv;
    }
    if (t < LL){
      float s=0.f;
      for (int j=0;j<NNB;j++){ float v=theta_s[t*NNB+j]; s+=v*v; }
      float inv = 1.0f/sqrtf(s);
      for (int j=0;j<NNB;j++) g_tnsT[j*LL+t] = theta_s[t*NNB+j]*inv;
    }
  }
}

// ------------------- kernel 2a v3: persistent split-bf16 mma.sync GEMM ----
// grid=160 blocks; each block loads B ONCE and processes 4 tiles of 128 rows.
#define GRID_LIN 160
#define NIT_LIN  4
#define SM_BIAS  0
#define SM_AHI   1024
#define SM_ALO   (SM_AHI + 128*136*2)
#define SM_BHI   (SM_ALO + 128*136*2)
#define SM_BLO   (SM_BHI + 192*136*2)
#define SMEM_LIN (SM_BLO + 192*136*2)      // 175104 bytes

__global__ __launch_bounds__(512)
void k_lin_mma(const float* features, const int* idxs)
{
  extern __shared__ char smem[];
  int tid = threadIdx.x;
  int wid = tid >> 5, lane = tid & 31;
  float* sBias = (float*)(smem + SM_BIAS);

  if (tid < 192) sBias[tid] = g_biasv[tid];
  {
    const uint4* src = (const uint4*)g_BtileH;
    uint4* dst = (uint4*)(smem + SM_BHI);
    #pragma unroll
    for (int i=0;i<13;i++){
      int u = tid + i*512;
      if (u < 6528) dst[u] = src[u];
    }
  }

  int wm = wid >> 1, wn = wid & 1;
  int mbase = wm*16, nbase = wn*96;
  uint32_t sb = smem_u32(smem);

  int aRow = mbase + ((lane>>3)&1)*8 + (lane&7);
  int aK   = (lane>>4)*8;
  int bRow = nbase + (lane&7);
  int bK   = ((lane>>3)&1)*8;
  int er = lane >> 2, ec2 = 2*(lane & 3);

  for (int it=0; it<NIT_LIN; it++){
    size_t row0 = (size_t)(blockIdx.x + it*GRID_LIN) * 128;
    __syncthreads();   // B ready (it=0) / previous MMA done reading A

    // gather A + hi/lo split (idx LDG is warp-broadcast: same row per 32 lanes)
    #pragma unroll
    for (int i=0;i<8;i++){
      int u = tid + i*512;
      int row = u >> 5, q = u & 31;
      int id = idxs[row0 + row];
      float4 v;
      if (id == NALL) v = make_float4(0.f,0.f,0.f,0.f);
      else v = *(const float4*)&features[(size_t)id*FIN + q*4];
      __nv_bfloat162 h01 = __floats2bfloat162_rn(v.x, v.y);
      __nv_bfloat162 h23 = __floats2bfloat162_rn(v.z, v.w);
      float2 f01 = __bfloat1622float2(h01);
      float2 f23 = __bfloat1622float2(h23);
      __nv_bfloat162 l01 = __floats2bfloat162_rn(v.x - f01.x, v.y - f01.y);
      __nv_bfloat162 l23 = __floats2bfloat162_rn(v.z - f23.x, v.w - f23.y);
      uint32_t off = (uint32_t)(row*136 + q*4)*2;
      *(__nv_bfloat162*)(smem + SM_AHI + off)     = h01;
      *(__nv_bfloat162*)(smem + SM_AHI + off + 4) = h23;
      *(__nv_bfloat162*)(smem + SM_ALO + off)     = l01;
      *(__nv_bfloat162*)(smem + SM_ALO + off + 4) = l23;
    }
    __syncthreads();

    float acc[12][4];
    #pragma unroll
    for (int j=0;j<12;j++)
      #pragma unroll
      for (int q=0;q<4;q++) acc[j][q]=0.f;

    #pragma unroll
    for (int kc=0; kc<8; kc++){
      uint32_t bf[12][2];
      #pragma unroll
      for (int j=0;j<12;j++)
        ldsm_x2(bf[j], sb + SM_BHI + (uint32_t)((bRow + j*8)*136 + kc*16 + bK)*2);
      uint32_t af[4];
      ldsm_x4(af, sb + SM_AHI + (uint32_t)(aRow*136 + kc*16 + aK)*2);
      #pragma unroll
      for (int j=0;j<12;j++) mma16816(acc[j], af, bf[j]);
      ldsm_x4(af, sb + SM_ALO + (uint32_t)(aRow*136 + kc*16 + aK)*2);
      #pragma unroll
      for (int j=0;j<12;j++) mma16816(acc[j], af, bf[j]);
    }
    #pragma unroll
    for (int kc=0; kc<8; kc++){
      uint32_t bf[12][2];
      #pragma unroll
      for (int j=0;j<12;j++)
        ldsm_x2(bf[j], sb + SM_BLO + (uint32_t)((bRow + j*8)*136 + kc*16 + bK)*2);
      uint32_t af[4];
      ldsm_x4(af, sb + SM_AHI + (uint32_t)(aRow*136 + kc*16 + aK)*2);
      #pragma unroll
      for (int j=0;j<12;j++) mma16816(acc[j], af, bf[j]);
    }

    // epilogue: direct coalesced float2 STG (4 lanes cover one 32B sector)
    {
      int rr = mbase + er;
      #pragma unroll
      for (int j=0;j<12;j++){
        int cc = nbase + j*8 + ec2;
        float b0 = sBias[cc], b1 = sBias[cc+1];
        *(float2*)&g_Hraw[(row0 + rr)*GN + cc]     = make_float2(acc[j][0]+b0, acc[j][1]+b1);
        *(float2*)&g_Hraw[(row0 + rr + 8)*GN + cc] = make_float2(acc[j][2]+b0, acc[j][3]+b1);
      }
    }
  }
}

// ------------------- fused kernel: [0,32) proto ; [32,1056) phase1b -------------------
#define PROTO_BLOCKS (KK/2)

__global__ __launch_bounds__(256)
void k_fused(const float* adj, const int* idxs,
             const float* lng, const float* lnb,
             const float* sg, const float* sb,
             const float* an_b1, const float* an_w2, const float* an_b2,
             const float* wn_w1, const float* wn_b1,
             const float* alpha_raw,
             const float* Wlin, const float* blin,
             const float* proto_root, const float* proto_neigh,
             const float* proto_rad, const float* proto_dn)
{
  __shared__ __align__(16) char sBuf[28032];
  int tid = threadIdx.x;

  if (blockIdx.x < PROTO_BLOCKS){
    int h = tid >> 7, tl = tid & 127;
    int k = blockIdx.x*2 + h;
    size_t pb = (size_t)k*KCAT;

    float (*sXT)[FIN][12]  = (float(*)[FIN][12])(sBuf);
    float (*sH)[MM][FIN]   = (float(*)[MM][FIN])(sBuf + 12288);
    float (*sPp)[NNB][LL]  = (float(*)[NNB][LL])(sBuf + 22528);
    float (*sC)[NNB][NNB]  = (float(*)[NNB][NNB])(sBuf + 24832);
    float (*sCS)[NNB][NNB] = (float(*)[NNB][NNB])(sBuf + 25480);
    float (*sRed)[4]       = (float(*)[4])(sBuf + 26128);

    sXT[h][tl][0] = proto_root[k*FIN + tl];
    for (int m=0;m<NNB;m++) sXT[h][tl][m+1] = proto_neigh[(k*NNB+m)*FIN + tl];
    __syncthreads();

    float acc[MM];
    {
      float bias = blin[tl];
      #pragma unroll
      for (int r=0;r<MM;r++) acc[r]=bias;
      for (int i=0;i<FIN;i++){
        float wv = Wlin[i*DXX+tl];
        float4 xa = *(const float4*)&sXT[h][i][0];
        float4 xb = *(const float4*)&sXT[h][i][4];
        float2 xc = *(const float2*)&sXT[h][i][8];
        acc[0]+=xa.x*wv; acc[1]+=xa.y*wv; acc[2]+=xa.z*wv; acc[3]+=xa.w*wv;
        acc[4]+=xb.x*wv; acc[5]+=xb.y*wv; acc[6]+=xb.z*wv; acc[7]+=xb.w*wv;
        acc[8]+=xc.x*wv; acc[9]+=xc.y*wv;
      }
    }
    #pragma unroll
    for (int r=0;r<MM;r++) sH[h][r][tl]=acc[r];
    __syncthreads();
    ln_rows(sH[h], MM, lng, lnb, tl);
    __syncthreads();

    st_hl(g_PbH, g_PbL, pb + 1152 + tl, sH[h][0][tl]);
    {
      float v = sH[h][0][tl]; v*=v;
      v = wredsum(v);
      if ((tl&31)==0) sRed[h][tl>>5]=v;
    }
    __syncthreads();
    if (tl==0) g_hproto_sq[k] = sRed[h][0]+sRed[h][1]+sRed[h][2]+sRed[h][3];
    if (tl<32){
      float v=0.f;
      for (int d=0;d<DXX;d++) v += sH[h][0][d]*wn_w1[(DXX+d)*32 + tl];
      g_hp[k*32+tl]=v;
    }
    for (int q=tl;q<NNB*LL;q+=128){
      int m=q/LL, l=q%LL;
      float v=0.f;
      for (int d=0;d<DXX;d++) v += sH[h][1+m][d]*g_tnxT[d*LL+l];
      sPp[h][m][l]=v;
    }
    __syncthreads();
    if (tl<LL){
      float vals[NNB];
      for (int m=0;m<NNB;m++) vals[m]=sPp[h][m][tl];
      sort9(vals);
      for (int j=0;j<NNB;j++){
        float v=vals[j];
        st_hl(g_PbH, g_PbL, pb + j*LL + tl, v);
        st_hl(g_PbH, g_PbL, pb + 288 + j*LL + tl, v*v);
      }
    }
    if (tl < 36){
      int p=tl, i=0;
      while (p >= NNB-1-i){ p -= NNB-1-i; i++; }
      int j = i+1+p;
      float x = proto_dn[tl*KK + k];
      float s = 1.0f/(1.0f+expf(-x));
      sC[h][i][j]=s; sC[h][j][i]=s;
    }
    if (tl < NNB) sC[h][tl][tl]=0.f;
    __syncthreads();
    if (tl < NNB){
      float c[NNB];
      for (int i=0;i<NNB;i++) c[i]=sC[h][i][tl];
      sort9(c);
      for (int i=0;i<NNB;i++) sCS[h][i][tl]=c[i];
    }
    __syncthreads();
    if (tl < NNB){
      float mu=0.f; for(int j=0;j<NNB;j++) mu+=sCS[h][tl][j]; mu*=(1.f/NNB);
      float var=0.f; for(int j=0;j<NNB;j++){float d=sCS[h][tl][j]-mu; var+=d*d;} var*=(1.f/NNB);
      float rstd = rsqrtf(var+1e-5f);
      for (int j=0;j<NNB;j++) sCS[h][tl][j] = (sCS[h][tl][j]-mu)*rstd*sg[j]+sb[j];
    }
    __syncthreads();
    if (tl<LL){
      float vals[NNB];
      for (int m=0;m<NNB;m++){
        float v=0.f;
        for (int j=0;j<NNB;j++) v += sCS[h][m][j]*g_tnsT[j*LL+tl];
        vals[m]=v;
      }
      sort9(vals);
      for (int j=0;j<NNB;j++){
        float v=vals[j];
        st_hl(g_PbH, g_PbL, pb + 576 + j*LL + tl, v);
        st_hl(g_PbH, g_PbL, pb + 864 + j*LL + tl, v*v);
      }
    }
    if (tl==0){
      float r[NNB];
      for (int j=0;j<NNB;j++) r[j]=proto_rad[k*NNB+j];
      sort9(r);
      for (int j=0;j<NNB;j++){
        st_hl(g_PbH, g_PbL, pb + 1280 + j, r[j]);
        st_hl(g_PbH, g_PbL, pb + 1289 + j, r[j]*r[j]);
      }
    }
    for (int u=tl; u<46; u+=128){
      g_PbH[pb + 1298 + u] = __float2bfloat16(0.f);
      g_PbL[pb + 1298 + u] = __float2bfloat16(0.f);
    }
    return;
  }

  // ================= phase1b branch: warp-per-b =================
  int w = tid >> 5, lane = tid & 31;
  int b = (blockIdx.x - PROTO_BLOCKS)*8 + w;
  size_t ab = (size_t)b*KCAT;

  float (*sDm)[MM][MM]   = (float(*)[MM][MM])(sBuf);
  float (*sHS)[NNB][NNB] = (float(*)[NNB][NNB])(sBuf + 3200);
  float (*sHn)[FIN]      = (float(*)[FIN])(sBuf + 5792);
  float (*sVm)[NNB]      = (float(*)[NNB])(sBuf + 9888);
  unsigned (*sNbr)[MM]   = (unsigned(*)[MM])(sBuf + 10176);
  float (*sTnsT)[32]     = (float(*)[32])(sBuf + 10496);
  float* sWn             = (float*)(sBuf + 11648);

  for (int u=tid; u<NNB*32; u+=256) sTnsT[u>>5][u&31] = g_tnsT[u];
  #pragma unroll
  for (int i=0;i<16;i++) sWn[tid + i*256] = wn_w1[tid + i*256];

  const float* HR = g_Hraw + (size_t)b*MM*GN;

  if (lane < MM){
    int idv = idxs[b*MM + lane];
    if (lane >= 1) sVm[w][lane-1] = (idv != NALL) ? 1.f : 0.f;
    unsigned nb=0;
    const float* arow = adj + (size_t)b*MM*MM + lane*MM;
    #pragma unroll
    for (int j=0;j<MM;j++) if (arow[j] > 1e-5f) nb |= (1u<<j);
    sNbr[w][lane]=nb;
  }
  __syncthreads();

  float vs = 0.f;
  #pragma unroll
  for (int j=0;j<NNB;j++) vs += sVm[w][j];
  float vsi = 1.f/(vs + 1e-9f);

  if (lane < MM){
    float drow[MM];
    #pragma unroll
    for (int j=0;j<MM;j++) drow[j] = (j==lane)?0.f:10.f;
    unsigned reach = 1u<<lane, frontier = 1u<<lane;
    for (int step=1; step<MM; step++){
      unsigned nxt=0;
      #pragma unroll
      for (int v=0;v<MM;v++) if (frontier & (1u<<v)) nxt |= sNbr[w][v];
      nxt &= ~reach;
      if (!nxt) break;
      #pragma unroll
      for (int v=0;v<MM;v++) if (nxt & (1u<<v)) drow[v]=(float)step;
      reach |= nxt; frontier = nxt;
    }
    #pragma unroll
    for (int j=0;j<MM;j++) sDm[w][lane][j]=drow[j];
  }
  __syncwarp();
  for (int q=lane; q<MM*MM; q+=32){
    int i=q/MM, j=q%MM;
    float fi = (i==0)?1.f:sVm[w][i-1];
    float fj = (j==0)?1.f:sVm[w][j-1];
    sDm[w][i][j] = (fi*fj>0.f) ? sDm[w][i][j]*0.1f : 1.0f;
  }
  __syncwarp();

  float sv[MM], qv[MM];
  float a00, a01, a02, a03;
  #pragma unroll
  for (int r=0;r<MM;r++){
    const float* Hr = HR + r*GN;
    float a0=Hr[lane], a1=Hr[lane+32], a2=Hr[lane+64], a3=Hr[lane+96];
    sv[r] = (a0+a1)+(a2+a3);
    qv[r] = (a0*a0+a1*a1)+(a2*a2+a3*a3);
    if (r==0){ a00=a0; a01=a1; a02=a2; a03=a3; }
  }
  #pragma unroll
  for (int o=16;o;o>>=1){
    #pragma unroll
    for (int r=0;r<MM;r++){
      sv[r] += __shfl_xor_sync(0xffffffffu, sv[r], o);
      qv[r] += __shfl_xor_sync(0xffffffffu, qv[r], o);
    }
  }
  float muv[NNB], rsv[NNB];
  float mu0 = sv[0]*(1.f/FIN);
  float rs0 = rsqrtf(fmaxf(qv[0]*(1.f/FIN) - mu0*mu0, 0.f) + 1e-5f);
  #pragma unroll
  for (int r=1;r<MM;r++){
    float mu = sv[r]*(1.f/FIN);
    muv[r-1] = mu;
    rsv[r-1] = rsqrtf(fmaxf(qv[r]*(1.f/FIN) - mu*mu, 0.f) + 1e-5f);
  }
  {
    float lg0=lng[lane], lg1=lng[lane+32], lg2=lng[lane+64], lg3=lng[lane+96];
    float lb0=lnb[lane], lb1=lnb[lane+32], lb2=lnb[lane+64], lb3=lnb[lane+96];
    float h0=(a00-mu0)*rs0*lg0+lb0, h1=(a01-mu0)*rs0*lg1+lb1;
    float h2=(a02-mu0)*rs0*lg2+lb2, h3=(a03-mu0)*rs0*lg3+lb3;
    sHn[w][lane]=h0; sHn[w][lane+32]=h1; sHn[w][lane+64]=h2; sHn[w][lane+96]=h3;
    st_hl(g_AbH, g_AbL, ab + 1152 + lane,      -2.f*h0);
    st_hl(g_AbH, g_AbL, ab + 1152 + lane + 32, -2.f*h1);
    st_hl(g_AbH, g_AbL, ab + 1152 + lane + 64, -2.f*h2);
    st_hl(g_AbH, g_AbL, ab + 1152 + lane + 96, -2.f*h3);
    float qq = wredsum((h0*h0+h1*h1)+(h2*h2+h3*h3));
    if (lane==0) g_hrootsq[b]=qq;
  }
  __syncwarp();

  if (lane < NNB){
    float c[NNB];
    #pragma unroll
    for (int i=0;i<NNB;i++) c[i]=sDm[w][1+i][1+lane];
    sort9(c);
    #pragma unroll
    for (int i=0;i<NNB;i++) sHS[w][i][lane]=c[i];
  }
  __syncwarp();
  if (lane < NNB){
    float mu=0.f;
    #pragma unroll
    for (int j=0;j<NNB;j++) mu+=sHS[w][lane][j];
    mu *= (1.f/NNB);
    float var=0.f;
    #pragma unroll
    for (int j=0;j<NNB;j++){ float d=sHS[w][lane][j]-mu; var+=d*d; }
    var *= (1.f/NNB);
    float rstd=rsqrtf(var+1e-5f);
    #pragma unroll
    for (int j=0;j<NNB;j++) sHS[w][lane][j]=(sHS[w][lane][j]-mu)*rstd*sg[j]+sb[j];
  }
  __syncwarp();

  {
    float cSgl=g_cSg[lane], cCbl=g_cCb[lane];
    float vals[NNB]; int ord[NNB];
    #pragma unroll
    for (int m=0;m<NNB;m++)
      vals[m] = rsv[m]*(HR[(1+m)*GN+128+lane] - muv[m]*cSgl) + cCbl;
    argsort9(vals, ord);
    float t1=0.f;
    #pragma unroll
    for (int j=0;j<NNB;j++){
      int mo=ord[j];
      float wv = sVm[w][mo]*vsi;
      float pv = vals[mo];
      st_hl(g_AbH, g_AbL, ab + j*LL + lane,       -2.f*wv*pv);
      st_hl(g_AbH, g_AbL, ab + 288 + j*LL + lane, wv);
      t1 += wv*pv*pv;
    }
    t1 = wredsum(t1);
    if (lane==0) g_T1feat[b]=t1;
  }
  {
    float vals[NNB]; int ord[NNB];
    #pragma unroll
    for (int m=0;m<NNB;m++){
      float v2=0.f;
      #pragma unroll
      for (int j=0;j<NNB;j++) v2 += sHS[w][m][j]*sTnsT[j][lane];
      vals[m]=v2;
    }
    argsort9(vals, ord);
    float t1=0.f;
    #pragma unroll
    for (int j=0;j<NNB;j++){
      int mo=ord[j];
      float wv = sVm[w][mo]*vsi;
      float pv = vals[mo];
      st_hl(g_AbH, g_AbL, ab + 576 + j*LL + lane, -2.f*wv*pv);
      st_hl(g_AbH, g_AbL, ab + 864 + j*LL + lane, wv);
      t1 += wv*pv*pv;
    }
    t1 = wredsum(t1);
    if (lane==0) g_T1str[b]=t1;
  }
  if (lane==0){
    float rb[NNB]; int ord[NNB];
    #pragma unroll
    for (int j=0;j<NNB;j++) rb[j]=sDm[w][0][1+j];
    argsort9(rb, ord);
    float S=0.f;
    #pragma unroll
    for (int j=0;j<NNB;j++){
      int mo=ord[j];
      float wv=sVm[w][mo]*vsi;
      float v=rb[mo];
      st_hl(g_AbH, g_AbL, ab + 1280 + j, -2.f*wv*v);
      st_hl(g_AbH, g_AbL, ab + 1289 + j, wv);
      S += wv*v*v;
    }
    g_Srad[b]=S;
  }
  for (int u=lane; u<46; u+=32){
    g_AbH[ab + 1298 + u] = __float2bfloat16(0.f);
    g_AbL[ab + 1298 + u] = __float2bfloat16(0.f);
  }
  {
    float v0 = wn_b1[lane], v1=0.f, v2=0.f, v3=0.f;
    #pragma unroll 8
    for (int d=0; d<DXX; d+=4){
      v0 += sHn[w][d+0]*sWn[(d+0)*32+lane];
      v1 += sHn[w][d+1]*sWn[(d+1)*32+lane];
      v2 += sHn[w][d+2]*sWn[(d+2)*32+lane];
      v3 += sHn[w][d+3]*sWn[(d+3)*32+lane];
    }
    g_hb[(size_t)b*32+lane] = (v0+v1)+(v2+v3);
  }
  {
    float cSga=g_cSg[32+lane], cCba=g_cCb[32+lane];
    float s=0.f;
    #pragma unroll
    for (int m=0;m<NNB;m++){
      float av = rsv[m]*(HR[(1+m)*GN+160+lane] - muv[m]*cSga) + cCba;
      s += sVm[w][m]*av;
    }
    float hid = fmaxf(an_b1[lane] + s*vsi, 0.f);
    float vv = wredsum(hid*an_w2[lane]);
    if (lane==0)
      g_alpha[b] = 1.0f/(1.0f+expf(-(alpha_raw[0] + vv + an_b2[0])));
  }
}

// ------------------- kernel 3 v4: tensor-core combine -------------------
#define TBM 32
#define P2_AHI 0
#define P2_ALO 4608
#define P2_PHI 9216
#define P2_PLO 18432
#define P2_TOT 27648

__device__ __forceinline__ void p2seg(int nch, int segbase, int b0,
    char* sm2, uint32_t sbm, int tid, int aRow, int aK, int bRow, int bK,
    float (*acc)[4])
{
  for (int ch=0; ch<nch; ch++){
    __syncthreads();
    {
      int row = tid>>3, q = tid&7;
      size_t src = (size_t)(b0+row)*KCAT + segbase + ch*64 + q*8;
      *(uint4*)(sm2 + P2_AHI + row*144 + q*16) = *(const uint4*)&g_AbH[src];
      *(uint4*)(sm2 + P2_ALO + row*144 + q*16) = *(const uint4*)&g_AbL[src];
    }
    #pragma unroll
    for (int i=0;i<2;i++){
      int u = tid + i*256;
      int row = u>>3, q = u&7;
      size_t src = (size_t)row*KCAT + segbase + ch*64 + q*8;
      *(uint4*)(sm2 + P2_PHI + row*144 + q*16) = *(const uint4*)&g_PbH[src];
      *(uint4*)(sm2 + P2_PLO + row*144 + q*16) = *(const uint4*)&g_PbL[src];
    }
    __syncthreads();
    #pragma unroll
    for (int ks=0; ks<4; ks++){
      uint32_t ah[4], al[4];
      ldsm_x4(ah, sbm + P2_AHI + (uint32_t)(aRow*144 + ks*32 + aK*2));
      ldsm_x4(al, sbm + P2_ALO + (uint32_t)(aRow*144 + ks*32 + aK*2));
      #pragma unroll
      for (int nt=0;nt<2;nt++){
        uint32_t ph[2], pl[2];
        ldsm_x2(ph, sbm + P2_PHI + (uint32_t)((bRow+nt*8)*144 + ks*32 + bK*2));
        ldsm_x2(pl, sbm + P2_PLO + (uint32_t)((bRow+nt*8)*144 + ks*32 + bK*2));
        mma16816(acc[nt], ah, ph);
        mma16816(acc[nt], al, ph);
        mma16816(acc[nt], ah, pl);
      }
    }
  }
}

__global__ __launch_bounds__(256)
void k_phase2(const float* wn_w2, const float* wn_b2, const float* w_raw,
              const float* log_gamma, float* out)
{
  __shared__ __align__(16) char sm2[P2_TOT];
  int tid = threadIdx.x, wid = tid>>5, lane = tid&31;
  int b0 = blockIdx.x * TBM;
  int wm = wid>>2, wn = wid&3;
  int mbase = wm*16, nbase = wn*16;
  uint32_t sbm = smem_u32(sm2);

  int aRow = mbase + (lane&7) + ((lane>>3)&1)*8;
  int aK   = (lane>>4)*8;
  int bRow = (lane&7);
  int bK   = ((lane>>3)&1)*8;
  bRow += nbase;

  float accF[2][4], accS[2][4], accR[2][4], accD[2][4];
  #pragma unroll
  for (int nt=0;nt<2;nt++)
    #pragma unroll
    for (int q=0;q<4;q++){ accF[nt][q]=0.f; accS[nt][q]=0.f; accR[nt][q]=0.f; accD[nt][q]=0.f; }

  p2seg(9, 0,    b0, sm2, sbm, tid, aRow, aK, bRow, bK, accF);
  p2seg(9, 576,  b0, sm2, sbm, tid, aRow, aK, bRow, bK, accS);
  p2seg(2, 1152, b0, sm2, sbm, tid, aRow, aK, bRow, bK, accR);
  p2seg(1, 1280, b0, sm2, sbm, tid, aRow, aK, bRow, bK, accD);
  __syncthreads();

  float* sHb   = (float*)sm2;
  float* sHp   = (float*)(sm2 + 4224);
  float* sScB  = (float*)(sm2 + 12672);
  float* sHpsq = (float*)(sm2 + 13312);
  float* sW2   = (float*)(sm2 + 13568);
  for (int idx=tid; idx<TBM*32; idx+=256){ int bb=idx>>5, j=idx&31; sHb[bb*33+j]=g_hb[(size_t)(b0+bb)*32+j]; }
  for (int idx=tid; idx<KK*32; idx+=256){ int kk=idx>>5, j=idx&31; sHp[kk*33+j]=g_hp[kk*32+j]; }
  if (tid < TBM*5){
    int bb=tid/5, q=tid%5, bgl=b0+bb;
    float v;
    switch(q){
      case 0: v=g_T1feat[bgl]; break;
      case 1: v=g_T1str[bgl];  break;
      case 2: v=g_Srad[bgl];   break;
      case 3: v=g_hrootsq[bgl];break;
      default:v=g_alpha[bgl];
    }
    sScB[bb*5+q]=v;
  }
  if (tid < KK) sHpsq[tid]=g_hproto_sq[tid];
  if (tid < 32) sW2[tid]=wn_w2[tid];
  __syncthreads();

  int r = lane>>2, c2 = 2*(lane&3);
  int row0 = mbase + r, row1 = row0 + 8;
  float wlog[2][2][2];
  #pragma unroll
  for (int hh=0;hh<2;hh++)
    #pragma unroll
    for (int nt=0;nt<2;nt++){ wlog[hh][nt][0]=0.f; wlog[hh][nt][1]=0.f; }
  #pragma unroll 4
  for (int j=0;j<32;j++){
    float w2 = sW2[j];
    float hb0 = sHb[row0*33+j], hb1 = sHb[row1*33+j];
    #pragma unroll
    for (int nt=0;nt<2;nt++){
      int c = nbase + nt*8 + c2;
      float hp0 = sHp[c*33+j], hp1 = sHp[(c+1)*33+j];
      wlog[0][nt][0] += fmaxf(hb0+hp0,0.f)*w2;
      wlog[0][nt][1] += fmaxf(hb0+hp1,0.f)*w2;
      wlog[1][nt][0] += fmaxf(hb1+hp0,0.f)*w2;
      wlog[1][nt][1] += fmaxf(hb1+hp1,0.f)*w2;
    }
  }

  float wraw = w_raw[0], wb2v = wn_b2[0];
  float gamma = expf(log_gamma[0]);

  #pragma unroll
  for (int hh=0;hh<2;hh++){
    int row = hh ? row1 : row0;
    int bg = b0 + row;
    float T1f=sScB[row*5+0], T1s=sScB[row*5+1], Sr=sScB[row*5+2];
    float hrsq=sScB[row*5+3], al=sScB[row*5+4];
    #pragma unroll
    for (int nt=0;nt<2;nt++){
      #pragma unroll
      for (int e=0;e<2;e++){
        int q = hh*2 + e;
        int col = nbase + nt*8 + c2 + e;
        float wgt = 1.f/(1.f+expf(-(wraw + wlog[hh][nt][e] + wb2v)));
        float drf = hrsq + sHpsq[col] + accR[nt][q];
        float swf = (T1f + accF[nt][q])*(1.f/(float)LL);
        float sws = (T1s + accS[nt][q])*(1.f/(float)LL);
        float radv = Sr + accD[nt][q];
        float df = wgt*drf + (1.f-wgt)*swf;
        float ds = wgt*radv + (1.f-wgt)*sws;
        float dfgw = al*df + (1.f-al)*ds;
        out[(size_t)bg*KK + col] = expf(-gamma*dfgw);
      }
    }
  }
}

// ------------------- launcher -------------------
extern "C" void kernel_launch(void* const* d_in, const int* in_sizes, int n_in,
                              void* d_out, int out_size)
{
  const float* adj        = (const float*)d_in[0];
  const float* features   = (const float*)d_in[1];
  const int*   idxs       = (const int*)  d_in[2];
  const float* x_lin_w    = (const float*)d_in[3];
  const float* x_lin_b    = (const float*)d_in[4];
  const float* x_ln_g     = (const float*)d_in[5];
  const float* x_ln_b     = (const float*)d_in[6];
  const float* s_ln_g     = (const float*)d_in[7];
  const float* s_ln_b     = (const float*)d_in[8];
  const float* theta_x    = (const float*)d_in[9];
  const float* theta_s    = (const float*)d_in[10];
  const float* alpha_raw  = (const float*)d_in[11];
  const float* an_w1      = (const float*)d_in[12];
  const float* an_b1      = (const float*)d_in[13];
  const float* an_w2      = (const float*)d_in[14];
  const float* an_b2      = (const float*)d_in[15];
  const float* wn_w1      = (const float*)d_in[16];
  const float* wn_b1      = (const float*)d_in[17];
  const float* wn_w2      = (const float*)d_in[18];
  const float* wn_b2      = (const float*)d_in[19];
  const float* w_raw      = (const float*)d_in[20];
  const float* proto_root = (const float*)d_in[21];
  const float* proto_neigh= (const float*)d_in[22];
  const float* proto_rad  = (const float*)d_in[23];
  const float* proto_dn   = (const float*)d_in[24];
  const float* log_gamma  = (const float*)d_in[25];
  float* out = (float*)d_out;

  cudaFuncSetAttribute(k_lin_mma, cudaFuncAttributeMaxDynamicSharedMemorySize, SMEM_LIN);

  k_prep<<<42,256>>>(x_lin_w, x_lin_b, x_ln_g, x_ln_b, an_w1, theta_x, theta_s);
  k_lin_mma<<<GRID_LIN, 512, SMEM_LIN>>>(features, idxs);
  k_fused<<<PROTO_BLOCKS + BB/8, 256>>>(adj, idxs, x_ln_g, x_ln_b, s_ln_g, s_ln_b,
                                        an_b1, an_w2, an_b2, wn_w1, wn_b1, alpha_raw,
                                        x_lin_w, x_lin_b, proto_root, proto_neigh,
                                        proto_rad, proto_dn);
  k_phase2<<<BB/TBM, 256>>>(wn_w2, wn_b2, w_raw, log_gamma, out);
}

// round 16
// speedup vs baseline: 1.1533x; 1.1533x over previous
#include <cuda_runtime.h>
#include <cuda_bf16.h>
#include <math.h>
#include <stdint.h>

#define BB   8192
#define MM   10
#define NNB  9
#define FIN  128
#define DXX  128
#define KK   64
#define LL   32
#define NALL 100000
#define GN   192
#define KCAT 1344     // feat 576 | str 576 | root 128 | rad 18 + pad 46

// ------------------- device scratch -------------------
__device__ float g_tnxT[FIN*LL];
__device__ float g_tnsT[NNB*LL];
__device__ float g_biasv[GN];
__device__ float g_cSg[64];
__device__ float g_cCb[64];
__device__ float g_Hraw[(size_t)BB*MM*GN];
__device__ __align__(16) __nv_bfloat16 g_BtileH[2*GN*136];

__device__ __align__(16) __nv_bfloat16 g_AbH[(size_t)BB*KCAT];
__device__ __align__(16) __nv_bfloat16 g_AbL[(size_t)BB*KCAT];
__device__ __align__(16) __nv_bfloat16 g_PbH[KK*KCAT];
__device__ __align__(16) __nv_bfloat16 g_PbL[KK*KCAT];

__device__ float g_hproto_sq[KK];
__device__ float g_hp[KK*32];
__device__ float g_hrootsq[BB];
__device__ float g_hb[BB*32];
__device__ float g_alpha[BB];
__device__ float g_T1feat[BB];
__device__ float g_T1str[BB];
__device__ float g_Srad[BB];

// ------------------- helpers -------------------
__device__ __forceinline__ void sort9(float* v){
  for (int a=1;a<NNB;a++){
    float x=v[a]; int c=a-1;
    while (c>=0 && v[c]>x){ v[c+1]=v[c]; c--; }
    v[c+1]=x;
  }
}
__device__ __forceinline__ void argsort9(const float* v, int* ord){
  for (int a=0;a<NNB;a++) ord[a]=a;
  for (int a=1;a<NNB;a++){
    int o=ord[a]; float x=v[o]; int c=a-1;
    while (c>=0 && v[ord[c]]>x){ ord[c+1]=ord[c]; c--; }
    ord[c+1]=o;
  }
}
__device__ __forceinline__ float wredsum(float v){
  #pragma unroll
  for (int o=16;o;o>>=1) v += __shfl_xor_sync(0xffffffffu, v, o);
  return v;
}
__device__ __forceinline__ void ln_rows(float (*sH)[FIN], int nrows,
                                        const float* g, const float* b, int t){
  int w = t>>5, lane = t&31;
  for (int r=w; r<nrows; r+=4){
    float s=0.f;
    for (int j=lane;j<FIN;j+=32) s += sH[r][j];
    s = wredsum(s);
    float mu = s*(1.f/FIN);
    float s2=0.f;
    for (int j=lane;j<FIN;j+=32){ float d=sH[r][j]-mu; s2 += d*d; }
    s2 = wredsum(s2);
    float rstd = rsqrtf(s2*(1.f/FIN)+1e-5f);
    for (int j=lane;j<FIN;j+=32) sH[r][j] = (sH[r][j]-mu)*rstd*g[j] + b[j];
  }
}
__device__ __forceinline__ uint32_t smem_u32(const void* p){
  uint32_t a;
  asm("{ .reg .u64 t; cvta.to.shared.u64 t, %1; cvt.u32.u64 %0, t; }" : "=r"(a) : "l"(p));
  return a;
}
__device__ __forceinline__ void st_hl(__nv_bfloat16* H, __nv_bfloat16* L, size_t i, float v){
  __nv_bfloat16 h = __float2bfloat16(v);
  H[i]=h; L[i]=__float2bfloat16(v - __bfloat162float(h));
}
// ---- sm_80-compatible tensor core ops ----
__device__ __forceinline__ void ldsm_x4(uint32_t* r, uint32_t addr){
  asm volatile("ldmatrix.sync.aligned.m8n8.x4.shared.b16 {%0,%1,%2,%3}, [%4];"
    : "=r"(r[0]),"=r"(r[1]),"=r"(r[2]),"=r"(r[3]) : "r"(addr));
}
__device__ __forceinline__ void ldsm_x2(uint32_t* r, uint32_t addr){
  asm volatile("ldmatrix.sync.aligned.m8n8.x2.shared.b16 {%0,%1}, [%2];"
    : "=r"(r[0]),"=r"(r[1]) : "r"(addr));
}
__device__ __forceinline__ void mma16816(float* c, const uint32_t* a, const uint32_t* b){
  asm volatile(
    "mma.sync.aligned.m16n8k16.row.col.f32.bf16.bf16.f32 "
    "{%0,%1,%2,%3}, {%4,%5,%6,%7}, {%8,%9}, {%0,%1,%2,%3};"
    : "+f"(c[0]),"+f"(c[1]),"+f"(c[2]),"+f"(c[3])
    : "r"(a[0]),"r"(a[1]),"r"(a[2]),"r"(a[3]), "r"(b[0]),"r"(b[1]));
}

// ------------------- kernel 0: prep -------------------
__global__ void k_prep(const float* Wlin, const float* blin,
                       const float* lng, const float* lnb,
                       const float* an_w1, const float* theta_x, const float* theta_s){
  int bid = blockIdx.x, t = threadIdx.x;
  if (bid < 32){
    __shared__ float sInv[32];
    int wq = t>>5, lq = t&31;
    for (int row=wq; row<32; row+=8){
      float s=0.f;
      for (int j=lq;j<FIN;j+=32){ float v=theta_x[row*FIN+j]; s+=v*v; }
      s = wredsum(s);
      if (lq==0) sInv[row] = 1.0f/sqrtf(s);
    }
    __syncthreads();
    int out = bid*256 + t;
    int i = out >> 6, c = out & 63;
    float acc = 0.f;
    if (c < 32){
      for (int d=0; d<FIN; d++)
        acc += Wlin[i*DXX + d] * (lng[d]*theta_x[c*FIN + d]);
      acc *= sInv[c];
    } else {
      for (int d=0; d<FIN; d++)
        acc += Wlin[i*DXX + d] * (lng[d]*an_w1[d*32 + (c-32)]);
    }
    __nv_bfloat16 hb = __float2bfloat16(acc);
    __nv_bfloat16 lb = __float2bfloat16(acc - __bfloat162float(hb));
    int n = 128 + c;
    g_BtileH[(0*GN + n)*136 + i] = hb;
    g_BtileH[(1*GN + n)*136 + i] = lb;
  } else if (bid < 40){
    int base = (bid-32)*2048;
    for (int it=0; it<8; it++){
      int u = base + t + it*256;
      float v = Wlin[u];
      int k = u >> 7, n = u & 127;
      __nv_bfloat16 hb = __float2bfloat16(v);
      __nv_bfloat16 lb = __float2bfloat16(v - __bfloat162float(hb));
      g_BtileH[(0*GN + n)*136 + k] = hb;
      g_BtileH[(1*GN + n)*136 + k] = lb;
    }
  } else if (bid == 40){
    if (t < 128) g_biasv[t] = blin[t];
    float inv = 1.f;
    if (t < 32){
      float s=0.f;
      for (int d=0; d<FIN; d++){ float v=theta_x[t*FIN+d]; s+=v*v; }
      inv = 1.0f/sqrtf(s);
    }
    if (t < 64){
      float bs=0.f, sg=0.f, cb=0.f;
      for (int d=0; d<FIN; d++){
        float th = (t<32) ? theta_x[t*FIN+d]*inv : an_w1[d*32 + (t-32)];
        float v = lng[d]*th;
        bs += blin[d]*v;
        sg += v;
        cb += lnb[d]*th;
      }
      g_biasv[128+t]=bs; g_cSg[t]=sg; g_cCb[t]=cb;
    }
  } else {
    int w=t>>5, lane=t&31;
    for (int row=w; row<LL; row+=8){
      float s=0.f;
      for (int j=lane;j<FIN;j+=32){ float v=theta_x[row*FIN+j]; s+=v*v; }
      s = wredsum(s);
      float inv = 1.0f/sqrtf(s);
      for (int j=lane;j<FIN;j+=32) g_tnxT[j*LL+row] = theta_x[row*FIN+j]*inv;
    }
    if (t < LL){
      float s=0.f;
      for (int j=0;j<NNB;j++){ float v=theta_s[t*NNB+j]; s+=v*v; }
      float inv = 1.0f/sqrtf(s);
      for (int j=0;j<NNB;j++) g_tnsT[j*LL+t] = theta_s[t*NNB+j]*inv;
    }
  }
}

// ------------------- kernel 2a v4: balanced persistent split-bf16 mma.sync GEMM ----
// grid=128 blocks x 5 tiles (128*5*128 = 81920 rows). One B load per block, zero
// wave quantization (single wave, every block does identical work).
#define GRID_LIN 128
#define NIT_LIN  5
#define SM_BIAS  0
#define SM_AHI   1024
#define SM_ALO   (SM_AHI + 128*136*2)
#define SM_BHI   (SM_ALO + 128*136*2)
#define SM_BLO   (SM_BHI + 192*136*2)
#define SMEM_LIN (SM_BLO + 192*136*2)      // 175104 bytes

__global__ __launch_bounds__(512)
void k_lin_mma(const float* features, const int* idxs)
{
  extern __shared__ char smem[];
  int tid = threadIdx.x;
  int wid = tid >> 5, lane = tid & 31;
  float* sBias = (float*)(smem + SM_BIAS);

  if (tid < 192) sBias[tid] = g_biasv[tid];
  {
    const uint4* src = (const uint4*)g_BtileH;
    uint4* dst = (uint4*)(smem + SM_BHI);
    #pragma unroll
    for (int i=0;i<13;i++){
      int u = tid + i*512;
      if (u < 6528) dst[u] = src[u];
    }
  }

  int wm = wid >> 1, wn = wid & 1;
  int mbase = wm*16, nbase = wn*96;
  uint32_t sb = smem_u32(smem);

  int aRow = mbase + ((lane>>3)&1)*8 + (lane&7);
  int aK   = (lane>>4)*8;
  int bRow = nbase + (lane&7);
  int bK   = ((lane>>3)&1)*8;
  int er = lane >> 2, ec2 = 2*(lane & 3);

  for (int it=0; it<NIT_LIN; it++){
    size_t row0 = (size_t)(blockIdx.x + it*GRID_LIN) * 128;
    __syncthreads();   // B ready (it=0) / previous MMA done reading A

    // gather A + hi/lo split (idx LDG is warp-broadcast: same row per 32 lanes)
    #pragma unroll
    for (int i=0;i<8;i++){
      int u = tid + i*512;
      int row = u >> 5, q = u & 31;
      int id = idxs[row0 + row];
      float4 v;
      if (id == NALL) v = make_float4(0.f,0.f,0.f,0.f);
      else v = *(const float4*)&features[(size_t)id*FIN + q*4];
      __nv_bfloat162 h01 = __floats2bfloat162_rn(v.x, v.y);
      __nv_bfloat162 h23 = __floats2bfloat162_rn(v.z, v.w);
      float2 f01 = __bfloat1622float2(h01);
      float2 f23 = __bfloat1622float2(h23);
      __nv_bfloat162 l01 = __floats2bfloat162_rn(v.x - f01.x, v.y - f01.y);
      __nv_bfloat162 l23 = __floats2bfloat162_rn(v.z - f23.x, v.w - f23.y);
      uint32_t off = (uint32_t)(row*136 + q*4)*2;
      *(__nv_bfloat162*)(smem + SM_AHI + off)     = h01;
      *(__nv_bfloat162*)(smem + SM_AHI + off + 4) = h23;
      *(__nv_bfloat162*)(smem + SM_ALO + off)     = l01;
      *(__nv_bfloat162*)(smem + SM_ALO + off + 4) = l23;
    }
    __syncthreads();

    float acc[12][4];
    #pragma unroll
    for (int j=0;j<12;j++)
      #pragma unroll
      for (int q=0;q<4;q++) acc[j][q]=0.f;

    #pragma unroll
    for (int kc=0; kc<8; kc++){
      uint32_t bf[12][2];
      #pragma unroll
      for (int j=0;j<12;j++)
        ldsm_x2(bf[j], sb + SM_BHI + (uint32_t)((bRow + j*8)*136 + kc*16 + bK)*2);
      uint32_t af[4];
      ldsm_x4(af, sb + SM_AHI + (uint32_t)(aRow*136 + kc*16 + aK)*2);
      #pragma unroll
      for (int j=0;j<12;j++) mma16816(acc[j], af, bf[j]);
      ldsm_x4(af, sb + SM_ALO + (uint32_t)(aRow*136 + kc*16 + aK)*2);
      #pragma unroll
      for (int j=0;j<12;j++) mma16816(acc[j], af, bf[j]);
    }
    #pragma unroll
    for (int kc=0; kc<8; kc++){
      uint32_t bf[12][2];
      #pragma unroll
      for (int j=0;j<12;j++)
        ldsm_x2(bf[j], sb + SM_BLO + (uint32_t)((bRow + j*8)*136 + kc*16 + bK)*2);
      uint32_t af[4];
      ldsm_x4(af, sb + SM_AHI + (uint32_t)(aRow*136 + kc*16 + aK)*2);
      #pragma unroll
      for (int j=0;j<12;j++) mma16816(acc[j], af, bf[j]);
    }

    // epilogue: direct coalesced float2 STG (4 lanes cover one 32B sector)
    {
      int rr = mbase + er;
      #pragma unroll
      for (int j=0;j<12;j++){
        int cc = nbase + j*8 + ec2;
        float b0 = sBias[cc], b1 = sBias[cc+1];
        *(float2*)&g_Hraw[(row0 + rr)*GN + cc]     = make_float2(acc[j][0]+b0, acc[j][1]+b1);
        *(float2*)&g_Hraw[(row0 + rr + 8)*GN + cc] = make_float2(acc[j][2]+b0, acc[j][3]+b1);
      }
    }
  }
}

// ------------------- fused kernel: [0,32) proto ; [32,1056) phase1b -------------------
#define PROTO_BLOCKS (KK/2)

__global__ __launch_bounds__(256)
void k_fused(const float* adj, const int* idxs,
             const float* lng, const float* lnb,
             const float* sg, const float* sb,
             const float* an_b1, const float* an_w2, const float* an_b2,
             const float* wn_w1, const float* wn_b1,
             const float* alpha_raw,
             const float* Wlin, const float* blin,
             const float* proto_root, const float* proto_neigh,
             const float* proto_rad, const float* proto_dn)
{
  __shared__ __align__(16) char sBuf[28032];
  int tid = threadIdx.x;

  if (blockIdx.x < PROTO_BLOCKS){
    int h = tid >> 7, tl = tid & 127;
    int k = blockIdx.x*2 + h;
    size_t pb = (size_t)k*KCAT;

    float (*sXT)[FIN][12]  = (float(*)[FIN][12])(sBuf);
    float (*sH)[MM][FIN]   = (float(*)[MM][FIN])(sBuf + 12288);
    float (*sPp)[NNB][LL]  = (float(*)[NNB][LL])(sBuf + 22528);
    float (*sC)[NNB][NNB]  = (float(*)[NNB][NNB])(sBuf + 24832);
    float (*sCS)[NNB][NNB] = (float(*)[NNB][NNB])(sBuf + 25480);
    float (*sRed)[4]       = (float(*)[4])(sBuf + 26128);

    sXT[h][tl][0] = proto_root[k*FIN + tl];
    for (int m=0;m<NNB;m++) sXT[h][tl][m+1] = proto_neigh[(k*NNB+m)*FIN + tl];
    __syncthreads();

    float acc[MM];
    {
      float bias = blin[tl];
      #pragma unroll
      for (int r=0;r<MM;r++) acc[r]=bias;
      for (int i=0;i<FIN;i++){
        float wv = Wlin[i*DXX+tl];
        float4 xa = *(const float4*)&sXT[h][i][0];
        float4 xb = *(const float4*)&sXT[h][i][4];
        float2 xc = *(const float2*)&sXT[h][i][8];
        acc[0]+=xa.x*wv; acc[1]+=xa.y*wv; acc[2]+=xa.z*wv; acc[3]+=xa.w*wv;
        acc[4]+=xb.x*wv; acc[5]+=xb.y*wv; acc[6]+=xb.z*wv; acc[7]+=xb.w*wv;
        acc[8]+=xc.x*wv; acc[9]+=xc.y*wv;
      }
    }
    #pragma unroll
    for (int r=0;r<MM;r++) sH[h][r][tl]=acc[r];
    __syncthreads();
    ln_rows(sH[h], MM, lng, lnb, tl);
    __syncthreads();

    st_hl(g_PbH, g_PbL, pb + 1152 + tl, sH[h][0][tl]);
    {
      float v = sH[h][0][tl]; v*=v;
      v = wredsum(v);
      if ((tl&31)==0) sRed[h][tl>>5]=v;
    }
    __syncthreads();
    if (tl==0) g_hproto_sq[k] = sRed[h][0]+sRed[h][1]+sRed[h][2]+sRed[h][3];
    if (tl<32){
      float v=0.f;
      for (int d=0;d<DXX;d++) v += sH[h][0][d]*wn_w1[(DXX+d)*32 + tl];
      g_hp[k*32+tl]=v;
    }
    for (int q=tl;q<NNB*LL;q+=128){
      int m=q/LL, l=q%LL;
      float v=0.f;
      for (int d=0;d<DXX;d++) v += sH[h][1+m][d]*g_tnxT[d*LL+l];
      sPp[h][m][l]=v;
    }
    __syncthreads();
    if (tl<LL){
      float vals[NNB];
      for (int m=0;m<NNB;m++) vals[m]=sPp[h][m][tl];
      sort9(vals);
      for (int j=0;j<NNB;j++){
        float v=vals[j];
        st_hl(g_PbH, g_PbL, pb + j*LL + tl, v);
        st_hl(g_PbH, g_PbL, pb + 288 + j*LL + tl, v*v);
      }
    }
    if (tl < 36){
      int p=tl, i=0;
      while (p >= NNB-1-i){ p -= NNB-1-i; i++; }
      int j = i+1+p;
      float x = proto_dn[tl*KK + k];
      float s = 1.0f/(1.0f+expf(-x));
      sC[h][i][j]=s; sC[h][j][i]=s;
    }
    if (tl < NNB) sC[h][tl][tl]=0.f;
    __syncthreads();
    if (tl < NNB){
      float c[NNB];
      for (int i=0;i<NNB;i++) c[i]=sC[h][i][tl];
      sort9(c);
      for (int i=0;i<NNB;i++) sCS[h][i][tl]=c[i];
    }
    __syncthreads();
    if (tl < NNB){
      float mu=0.f; for(int j=0;j<NNB;j++) mu+=sCS[h][tl][j]; mu*=(1.f/NNB);
      float var=0.f; for(int j=0;j<NNB;j++){float d=sCS[h][tl][j]-mu; var+=d*d;} var*=(1.f/NNB);
      float rstd = rsqrtf(var+1e-5f);
      for (int j=0;j<NNB;j++) sCS[h][tl][j] = (sCS[h][tl][j]-mu)*rstd*sg[j]+sb[j];
    }
    __syncthreads();
    if (tl<LL){
      float vals[NNB];
      for (int m=0;m<NNB;m++){
        float v=0.f;
        for (int j=0;j<NNB;j++) v += sCS[h][m][j]*g_tnsT[j*LL+tl];
        vals[m]=v;
      }
      sort9(vals);
      for (int j=0;j<NNB;j++){
        float v=vals[j];
        st_hl(g_PbH, g_PbL, pb + 576 + j*LL + tl, v);
        st_hl(g_PbH, g_PbL, pb + 864 + j*LL + tl, v*v);
      }
    }
    if (tl==0){
      float r[NNB];
      for (int j=0;j<NNB;j++) r[j]=proto_rad[k*NNB+j];
      sort9(r);
      for (int j=0;j<NNB;j++){
        st_hl(g_PbH, g_PbL, pb + 1280 + j, r[j]);
        st_hl(g_PbH, g_PbL, pb + 1289 + j, r[j]*r[j]);
      }
    }
    for (int u=tl; u<46; u+=128){
      g_PbH[pb + 1298 + u] = __float2bfloat16(0.f);
      g_PbL[pb + 1298 + u] = __float2bfloat16(0.f);
    }
    return;
  }

  // ================= phase1b branch: warp-per-b =================
  int w = tid >> 5, lane = tid & 31;
  int b = (blockIdx.x - PROTO_BLOCKS)*8 + w;
  size_t ab = (size_t)b*KCAT;

  float (*sDm)[MM][MM]   = (float(*)[MM][MM])(sBuf);
  float (*sHS)[NNB][NNB] = (float(*)[NNB][NNB])(sBuf + 3200);
  float (*sHn)[FIN]      = (float(*)[FIN])(sBuf + 5792);
  float (*sVm)[NNB]      = (float(*)[NNB])(sBuf + 9888);
  unsigned (*sNbr)[MM]   = (unsigned(*)[MM])(sBuf + 10176);
  float (*sTnsT)[32]     = (float(*)[32])(sBuf + 10496);
  float* sWn             = (float*)(sBuf + 11648);

  for (int u=tid; u<NNB*32; u+=256) sTnsT[u>>5][u&31] = g_tnsT[u];
  #pragma unroll
  for (int i=0;i<16;i++) sWn[tid + i*256] = wn_w1[tid + i*256];

  const float* HR = g_Hraw + (size_t)b*MM*GN;

  if (lane < MM){
    int idv = idxs[b*MM + lane];
    if (lane >= 1) sVm[w][lane-1] = (idv != NALL) ? 1.f : 0.f;
    unsigned nb=0;
    const float* arow = adj + (size_t)b*MM*MM + lane*MM;
    #pragma unroll
    for (int j=0;j<MM;j++) if (arow[j] > 1e-5f) nb |= (1u<<j);
    sNbr[w][lane]=nb;
  }
  __syncthreads();

  float vs = 0.f;
  #pragma unroll
  for (int j=0;j<NNB;j++) vs += sVm[w][j];
  float vsi = 1.f/(vs + 1e-9f);

  if (lane < MM){
    float drow[MM];
    #pragma unroll
    for (int j=0;j<MM;j++) drow[j] = (j==lane)?0.f:10.f;
    unsigned reach = 1u<<lane, frontier = 1u<<lane;
    for (int step=1; step<MM; step++){
      unsigned nxt=0;
      #pragma unroll
      for (int v=0;v<MM;v++) if (frontier & (1u<<v)) nxt |= sNbr[w][v];
      nxt &= ~reach;
      if (!nxt) break;
      #pragma unroll
      for (int v=0;v<MM;v++) if (nxt & (1u<<v)) drow[v]=(float)step;
      reach |= nxt; frontier = nxt;
    }
    #pragma unroll
    for (int j=0;j<MM;j++) sDm[w][lane][j]=drow[j];
  }
  __syncwarp();
  for (int q=lane; q<MM*MM; q+=32){
    int i=q/MM, j=q%MM;
    float fi = (i==0)?1.f:sVm[w][i-1];
    float fj = (j==0)?1.f:sVm[w][j-1];
    sDm[w][i][j] = (fi*fj>0.f) ? sDm[w][i][j]*0.1f : 1.0f;
  }
  __syncwarp();

  float sv[MM], qv[MM];
  float a00, a01, a02, a03;
  #pragma unroll
  for (int r=0;r<MM;r++){
    const float* Hr = HR + r*GN;
    float a0=Hr[lane], a1=Hr[lane+32], a2=Hr[lane+64], a3=Hr[lane+96];
    sv[r] = (a0+a1)+(a2+a3);
    qv[r] = (a0*a0+a1*a1)+(a2*a2+a3*a3);
    if (r==0){ a00=a0; a01=a1; a02=a2; a03=a3; }
  }
  #pragma unroll
  for (int o=16;o;o>>=1){
    #pragma unroll
    for (int r=0;r<MM;r++){
      sv[r] += __shfl_xor_sync(0xffffffffu, sv[r], o);
      qv[r] += __shfl_xor_sync(0xffffffffu, qv[r], o);
    }
  }
  float muv[NNB], rsv[NNB];
  float mu0 = sv[0]*(1.f/FIN);
  float rs0 = rsqrtf(fmaxf(qv[0]*(1.f/FIN) - mu0*mu0, 0.f) + 1e-5f);
  #pragma unroll
  for (int r=1;r<MM;r++){
    float mu = sv[r]*(1.f/FIN);
    muv[r-1] = mu;
    rsv[r-1] = rsqrtf(fmaxf(qv[r]*(1.f/FIN) - mu*mu, 0.f) + 1e-5f);
  }
  {
    float lg0=lng[lane], lg1=lng[lane+32], lg2=lng[lane+64], lg3=lng[lane+96];
    float lb0=lnb[lane], lb1=lnb[lane+32], lb2=lnb[lane+64], lb3=lnb[lane+96];
    float h0=(a00-mu0)*rs0*lg0+lb0, h1=(a01-mu0)*rs0*lg1+lb1;
    float h2=(a02-mu0)*rs0*lg2+lb2, h3=(a03-mu0)*rs0*lg3+lb3;
    sHn[w][lane]=h0; sHn[w][lane+32]=h1; sHn[w][lane+64]=h2; sHn[w][lane+96]=h3;
    st_hl(g_AbH, g_AbL, ab + 1152 + lane,      -2.f*h0);
    st_hl(g_AbH, g_AbL, ab + 1152 + lane + 32, -2.f*h1);
    st_hl(g_AbH, g_AbL, ab + 1152 + lane + 64, -2.f*h2);
    st_hl(g_AbH, g_AbL, ab + 1152 + lane + 96, -2.f*h3);
    float qq = wredsum((h0*h0+h1*h1)+(h2*h2+h3*h3));
    if (lane==0) g_hrootsq[b]=qq;
  }
  __syncwarp();

  if (lane < NNB){
    float c[NNB];
    #pragma unroll
    for (int i=0;i<NNB;i++) c[i]=sDm[w][1+i][1+lane];
    sort9(c);
    #pragma unroll
    for (int i=0;i<NNB;i++) sHS[w][i][lane]=c[i];
  }
  __syncwarp();
  if (lane < NNB){
    float mu=0.f;
    #pragma unroll
    for (int j=0;j<NNB;j++) mu+=sHS[w][lane][j];
    mu *= (1.f/NNB);
    float var=0.f;
    #pragma unroll
    for (int j=0;j<NNB;j++){ float d=sHS[w][lane][j]-mu; var+=d*d; }
    var *= (1.f/NNB);
    float rstd=rsqrtf(var+1e-5f);
    #pragma unroll
    for (int j=0;j<NNB;j++) sHS[w][lane][j]=(sHS[w][lane][j]-mu)*rstd*sg[j]+sb[j];
  }
  __syncwarp();

  {
    float cSgl=g_cSg[lane], cCbl=g_cCb[lane];
    float vals[NNB]; int ord[NNB];
    #pragma unroll
    for (int m=0;m<NNB;m++)
      vals[m] = rsv[m]*(HR[(1+m)*GN+128+lane] - muv[m]*cSgl) + cCbl;
    argsort9(vals, ord);
    float t1=0.f;
    #pragma unroll
    for (int j=0;j<NNB;j++){
      int mo=ord[j];
      float wv = sVm[w][mo]*vsi;
      float pv = vals[mo];
      st_hl(g_AbH, g_AbL, ab + j*LL + lane,       -2.f*wv*pv);
      st_hl(g_AbH, g_AbL, ab + 288 + j*LL + lane, wv);
      t1 += wv*pv*pv;
    }
    t1 = wredsum(t1);
    if (lane==0) g_T1feat[b]=t1;
  }
  {
    float vals[NNB]; int ord[NNB];
    #pragma unroll
    for (int m=0;m<NNB;m++){
      float v2=0.f;
      #pragma unroll
      for (int j=0;j<NNB;j++) v2 += sHS[w][m][j]*sTnsT[j][lane];
      vals[m]=v2;
    }
    argsort9(vals, ord);
    float t1=0.f;
    #pragma unroll
    for (int j=0;j<NNB;j++){
      int mo=ord[j];
      float wv = sVm[w][mo]*vsi;
      float pv = vals[mo];
      st_hl(g_AbH, g_AbL, ab + 576 + j*LL + lane, -2.f*wv*pv);
      st_hl(g_AbH, g_AbL, ab + 864 + j*LL + lane, wv);
      t1 += wv*pv*pv;
    }
    t1 = wredsum(t1);
    if (lane==0) g_T1str[b]=t1;
  }
  if (lane==0){
    float rb[NNB]; int ord[NNB];
    #pragma unroll
    for (int j=0;j<NNB;j++) rb[j]=sDm[w][0][1+j];
    argsort9(rb, ord);
    float S=0.f;
    #pragma unroll
    for (int j=0;j<NNB;j++){
      int mo=ord[j];
      float wv=sVm[w][mo]*vsi;
      float v=rb[mo];
      st_hl(g_AbH, g_AbL, ab + 1280 + j, -2.f*wv*v);
      st_hl(g_AbH, g_AbL, ab + 1289 + j, wv);
      S += wv*v*v;
    }
    g_Srad[b]=S;
  }
  for (int u=lane; u<46; u+=32){
    g_AbH[ab + 1298 + u] = __float2bfloat16(0.f);
    g_AbL[ab + 1298 + u] = __float2bfloat16(0.f);
  }
  {
    float v0 = wn_b1[lane], v1=0.f, v2=0.f, v3=0.f;
    #pragma unroll 8
    for (int d=0; d<DXX; d+=4){
      v0 += sHn[w][d+0]*sWn[(d+0)*32+lane];
      v1 += sHn[w][d+1]*sWn[(d+1)*32+lane];
      v2 += sHn[w][d+2]*sWn[(d+2)*32+lane];
      v3 += sHn[w][d+3]*sWn[(d+3)*32+lane];
    }
    g_hb[(size_t)b*32+lane] = (v0+v1)+(v2+v3);
  }
  {
    float cSga=g_cSg[32+lane], cCba=g_cCb[32+lane];
    float s=0.f;
    #pragma unroll
    for (int m=0;m<NNB;m++){
      float av = rsv[m]*(HR[(1+m)*GN+160+lane] - muv[m]*cSga) + cCba;
      s += sVm[w][m]*av;
    }
    float hid = fmaxf(an_b1[lane] + s*vsi, 0.f);
    float vv = wredsum(hid*an_w2[lane]);
    if (lane==0)
      g_alpha[b] = 1.0f/(1.0f+expf(-(alpha_raw[0] + vv + an_b2[0])));
  }
}

// ------------------- kernel 3 v4: tensor-core combine -------------------
#define TBM 32
#define P2_AHI 0
#define P2_ALO 4608
#define P2_PHI 9216
#define P2_PLO 18432
#define P2_TOT 27648

__device__ __forceinline__ void p2seg(int nch, int segbase, int b0,
    char* sm2, uint32_t sbm, int tid, int aRow, int aK, int bRow, int bK,
    float (*acc)[4])
{
  for (int ch=0; ch<nch; ch++){
    __syncthreads();
    {
      int row = tid>>3, q = tid&7;
      size_t src = (size_t)(b0+row)*KCAT + segbase + ch*64 + q*8;
      *(uint4*)(sm2 + P2_AHI + row*144 + q*16) = *(const uint4*)&g_AbH[src];
      *(uint4*)(sm2 + P2_ALO + row*144 + q*16) = *(const uint4*)&g_AbL[src];
    }
    #pragma unroll
    for (int i=0;i<2;i++){
      int u = tid + i*256;
      int row = u>>3, q = u&7;
      size_t src = (size_t)row*KCAT + segbase + ch*64 + q*8;
      *(uint4*)(sm2 + P2_PHI + row*144 + q*16) = *(const uint4*)&g_PbH[src];
      *(uint4*)(sm2 + P2_PLO + row*144 + q*16) = *(const uint4*)&g_PbL[src];
    }
    __syncthreads();
    #pragma unroll
    for (int ks=0; ks<4; ks++){
      uint32_t ah[4], al[4];
      ldsm_x4(ah, sbm + P2_AHI + (uint32_t)(aRow*144 + ks*32 + aK*2));
      ldsm_x4(al, sbm + P2_ALO + (uint32_t)(aRow*144 + ks*32 + aK*2));
      #pragma unroll
      for (int nt=0;nt<2;nt++){
        uint32_t ph[2], pl[2];
        ldsm_x2(ph, sbm + P2_PHI + (uint32_t)((bRow+nt*8)*144 + ks*32 + bK*2));
        ldsm_x2(pl, sbm + P2_PLO + (uint32_t)((bRow+nt*8)*144 + ks*32 + bK*2));
        mma16816(acc[nt], ah, ph);
        mma16816(acc[nt], al, ph);
        mma16816(acc[nt], ah, pl);
      }
    }
  }
}

__global__ __launch_bounds__(256)
void k_phase2(const float* wn_w2, const float* wn_b2, const float* w_raw,
              const float* log_gamma, float* out)
{
  __shared__ __align__(16) char sm2[P2_TOT];
  int tid = threadIdx.x, wid = tid>>5, lane = tid&31;
  int b0 = blockIdx.x * TBM;
  int wm = wid>>2, wn = wid&3;
  int mbase = wm*16, nbase = wn*16;
  uint32_t sbm = smem_u32(sm2);

  int aRow = mbase + (lane&7) + ((lane>>3)&1)*8;
  int aK   = (lane>>4)*8;
  int bRow = (lane&7);
  int bK   = ((lane>>3)&1)*8;
  bRow += nbase;

  float accF[2][4], accS[2][4], accR[2][4], accD[2][4];
  #pragma unroll
  for (int nt=0;nt<2;nt++)
    #pragma unroll
    for (int q=0;q<4;q++){ accF[nt][q]=0.f; accS[nt][q]=0.f; accR[nt][q]=0.f; accD[nt][q]=0.f; }

  p2seg(9, 0,    b0, sm2, sbm, tid, aRow, aK, bRow, bK, accF);
  p2seg(9, 576,  b0, sm2, sbm, tid, aRow, aK, bRow, bK, accS);
  p2seg(2, 1152, b0, sm2, sbm, tid, aRow, aK, bRow, bK, accR);
  p2seg(1, 1280, b0, sm2, sbm, tid, aRow, aK, bRow, bK, accD);
  __syncthreads();

  float* sHb   = (float*)sm2;
  float* sHp   = (float*)(sm2 + 4224);
  float* sScB  = (float*)(sm2 + 12672);
  float* sHpsq = (float*)(sm2 + 13312);
  float* sW2   = (float*)(sm2 + 13568);
  for (int idx=tid; idx<TBM*32; idx+=256){ int bb=idx>>5, j=idx&31; sHb[bb*33+j]=g_hb[(size_t)(b0+bb)*32+j]; }
  for (int idx=tid; idx<KK*32; idx+=256){ int kk=idx>>5, j=idx&31; sHp[kk*33+j]=g_hp[kk*32+j]; }
  if (tid < TBM*5){
    int bb=tid/5, q=tid%5, bgl=b0+bb;
    float v;
    switch(q){
      case 0: v=g_T1feat[bgl]; break;
      case 1: v=g_T1str[bgl];  break;
      case 2: v=g_Srad[bgl];   break;
      case 3: v=g_hrootsq[bgl];break;
      default:v=g_alpha[bgl];
    }
    sScB[bb*5+q]=v;
  }
  if (tid < KK) sHpsq[tid]=g_hproto_sq[tid];
  if (tid < 32) sW2[tid]=wn_w2[tid];
  __syncthreads();

  int r = lane>>2, c2 = 2*(lane&3);
  int row0 = mbase + r, row1 = row0 + 8;
  float wlog[2][2][2];
  #pragma unroll
  for (int hh=0;hh<2;hh++)
    #pragma unroll
    for (int nt=0;nt<2;nt++){ wlog[hh][nt][0]=0.f; wlog[hh][nt][1]=0.f; }
  #pragma unroll 4
  for (int j=0;j<32;j++){
    float w2 = sW2[j];
    float hb0 = sHb[row0*33+j], hb1 = sHb[row1*33+j];
    #pragma unroll
    for (int nt=0;nt<2;nt++){
      int c = nbase + nt*8 + c2;
      float hp0 = sHp[c*33+j], hp1 = sHp[(c+1)*33+j];
      wlog[0][nt][0] += fmaxf(hb0+hp0,0.f)*w2;
      wlog[0][nt][1] += fmaxf(hb0+hp1,0.f)*w2;
      wlog[1][nt][0] += fmaxf(hb1+hp0,0.f)*w2;
      wlog[1][nt][1] += fmaxf(hb1+hp1,0.f)*w2;
    }
  }

  float wraw = w_raw[0], wb2v = wn_b2[0];
  float gamma = expf(log_gamma[0]);

  #pragma unroll
  for (int hh=0;hh<2;hh++){
    int row = hh ? row1 : row0;
    int bg = b0 + row;
    float T1f=sScB[row*5+0], T1s=sScB[row*5+1], Sr=sScB[row*5+2];
    float hrsq=sScB[row*5+3], al=sScB[row*5+4];
    #pragma unroll
    for (int nt=0;nt<2;nt++){
      #pragma unroll
      for (int e=0;e<2;e++){
        int q = hh*2 + e;
        int col = nbase + nt*8 + c2 + e;
        float wgt = 1.f/(1.f+expf(-(wraw + wlog[hh][nt][e] + wb2v)));
        float drf = hrsq + sHpsq[col] + accR[nt][q];
        float swf = (T1f + accF[nt][q])*(1.f/(float)LL);
        float sws = (T1s + accS[nt][q])*(1.f/(float)LL);
        float radv = Sr + accD[nt][q];
        float df = wgt*drf + (1.f-wgt)*swf;
        float ds = wgt*radv + (1.f-wgt)*sws;
        float dfgw = al*df + (1.f-al)*ds;
        out[(size_t)bg*KK + col] = expf(-gamma*dfgw);
      }
    }
  }
}

// ------------------- launcher -------------------
extern "C" void kernel_launch(void* const* d_in, const int* in_sizes, int n_in,
                              void* d_out, int out_size)
{
  const float* adj        = (const float*)d_in[0];
  const float* features   = (const float*)d_in[1];
  const int*   idxs       = (const int*)  d_in[2];
  const float* x_lin_w    = (const float*)d_in[3];
  const float* x_lin_b    = (const float*)d_in[4];
  const float* x_ln_g     = (const float*)d_in[5];
  const float* x_ln_b     = (const float*)d_in[6];
  const float* s_ln_g     = (const float*)d_in[7];
  const float* s_ln_b     = (const float*)d_in[8];
  const float* theta_x    = (const float*)d_in[9];
  const float* theta_s    = (const float*)d_in[10];
  const float* alpha_raw  = (const float*)d_in[11];
  const float* an_w1      = (const float*)d_in[12];
  const float* an_b1      = (const float*)d_in[13];
  const float* an_w2      = (const float*)d_in[14];
  const float* an_b2      = (const float*)d_in[15];
  const float* wn_w1      = (const float*)d_in[16];
  const float* wn_b1      = (const float*)d_in[17];
  const float* wn_w2      = (const float*)d_in[18];
  const float* wn_b2      = (const float*)d_in[19];
  const float* w_raw      = (const float*)d_in[20];
  const float* proto_root = (const float*)d_in[21];
  const float* proto_neigh= (const float*)d_in[22];
  const float* proto_rad  = (const float*)d_in[23];
  const float* proto_dn   = (const float*)d_in[24];
  const float* log_gamma  = (const float*)d_in[25];
  float* out = (float*)d_out;

  cudaFuncSetAttribute(k_lin_mma, cudaFuncAttributeMaxDynamicSharedMemorySize, SMEM_LIN);

  k_prep<<<42,256>>>(x_lin_w, x_lin_b, x_ln_g, x_ln_b, an_w1, theta_x, theta_s);
  k_lin_mma<<<GRID_LIN, 512, SMEM_LIN>>>(features, idxs);
  k_fused<<<PROTO_BLOCKS + BB/8, 256>>>(adj, idxs, x_ln_g, x_ln_b, s_ln_g, s_ln_b,
                                        an_b1, an_w2, an_b2, wn_w1, wn_b1, alpha_raw,
                                        x_lin_w, x_lin_b, proto_root, proto_neigh,
                                        proto_rad, proto_dn);
  k_phase2<<<BB/TBM, 256>>>(wn_w2, wn_b2, w_raw, log_gamma, out);
}